// round 11
// baseline (speedup 1.0000x reference)
#include <cuda_runtime.h>
#include <cstdint>

#define NQ      8
#define NLAYERS 4
#define DIN     1024
#define DOUT    1024

using ull = unsigned long long;
#define SGN2 0x8000000080000000ULL

// ---------------- packed f32x2 helpers (Blackwell dual-FP32) ----------------
__device__ __forceinline__ ull pk(float x, float y) {
    ull r; asm("mov.b64 %0,{%1,%2};" : "=l"(r) : "f"(x), "f"(y)); return r;
}
__device__ __forceinline__ void up2(ull a, float& x, float& y) {
    asm("mov.b64 {%0,%1},%2;" : "=f"(x), "=f"(y) : "l"(a));
}
__device__ __forceinline__ ull dup2(float x) { return pk(x, x); }
__device__ __forceinline__ ull fma2(ull a, ull b, ull c) {
    ull d; asm("fma.rn.f32x2 %0,%1,%2,%3;" : "=l"(d) : "l"(a), "l"(b), "l"(c)); return d;
}
__device__ __forceinline__ ull mul2(ull a, ull b) {
    ull d; asm("mul.rn.f32x2 %0,%1,%2;" : "=l"(d) : "l"(a), "l"(b)); return d;
}
__device__ __forceinline__ ull add2(ull a, ull b) {
    ull d; asm("add.rn.f32x2 %0,%1,%2;" : "=l"(d) : "l"(a), "l"(b)); return d;
}
__device__ __forceinline__ ull sub2(ull a, ull b) { return add2(a, b ^ SGN2); }
__device__ __forceinline__ ull swp(ull a) { float x, y; up2(a, x, y); return pk(y, x); }
__device__ __forceinline__ ull shflx(ull a, int m) {
    float x, y; up2(a, x, y);
    x = __shfl_xor_sync(0xffffffffu, x, m);
    y = __shfl_xor_sync(0xffffffffu, y, m);
    return pk(x, y);
}

// ================= gate butterfly (16 lanes/row, 16 amps/lane) =============
// Physical amp p[7:0]: bits 7..4 = group-lane l[3:0], bits 3..0 = local r.
// Packed pairs over bit0: reg j = r>>1 (8 ull per component).
// Gate mask M, parity row R: new[p] = d(b)*old[p] + o(b)*old[p^M], b=popc(p&R).
// Conjugate structure (u11=conj u00, u10=-conj u01): parity flips sign of
// (di, or) only.
template<int M, int R>
__device__ __forceinline__ void apply_gate8(ull* Ar, ull* Ai, float4 u, int l)
{
    constexpr int lm    = M >> 4;
    constexpr int loj   = (M & 15) >> 1;
    constexpr int lo0   = M & 1;
    constexpr int Rlane = R >> 4;
    constexpr int Rj    = (R & 15) >> 1;
    constexpr int R0    = R & 1;

    const bool pl = (__popc(l & Rlane) & 1) != 0;

    const ull drP  = dup2(u.x);
    const ull oiP  = dup2(u.w);
    const ull noiP = oiP ^ SGN2;
    ull diB = (R0 == 0) ? dup2(u.y) : pk(u.y, -u.y);
    ull orB = (R0 == 0) ? dup2(u.z) : pk(u.z, -u.z);
    if (pl) { diB ^= SGN2; orB ^= SGN2; }
    const ull diN = diB ^ SGN2, orN = orB ^ SGN2;

#define GUPD(jj, PR, PI)                                                        \
    {   const bool sj = (__popc((jj) & Rj) & 1) != 0;                           \
        const ull dij = sj ? diN : diB, ndij = sj ? diB : diN;                  \
        const ull orj = sj ? orN : orB;                                         \
        ull mr = Ar[jj], mi = Ai[jj];                                           \
        Ar[jj] = fma2(orj, PR, fma2(noiP, PI, fma2(ndij, mi, mul2(drP, mr))));  \
        Ai[jj] = fma2(oiP, PR, fma2(orj,  PI, fma2(dij,  mr, mul2(drP, mi)))); }

    if (loj == 0) {
#pragma unroll
        for (int j = 0; j < 8; j++) {
            ull Pr = Ar[j], Pi_ = Ai[j];
            if (lo0) { Pr = swp(Pr); Pi_ = swp(Pi_); }
            if (lm)  { Pr = shflx(Pr, lm); Pi_ = shflx(Pi_, lm); }
            GUPD(j, Pr, Pi_)
        }
    } else {
#pragma unroll
        for (int j = 0; j < 8; j++) {
            const int j2 = j ^ loj;
            if (j < j2) {
                ull Par = Ar[j2], Pai = Ai[j2];
                ull Pbr = Ar[j],  Pbi = Ai[j];
                if (lo0) { Par = swp(Par); Pai = swp(Pai); Pbr = swp(Pbr); Pbi = swp(Pbi); }
                if (lm)  { Par = shflx(Par, lm); Pai = shflx(Pai, lm);
                           Pbr = shflx(Pbr, lm); Pbi = shflx(Pbi, lm); }
                GUPD(j,  Par, Pai)
                GUPD(j2, Pbr, Pbi)
            }
        }
    }
#undef GUPD
}

// ================= fused kernel: angles + circuit + output GEMM ============
// Block = 128 threads, 8 rows. Block b owns rows 8b..8b+7 end-to-end.
__global__ __launch_bounds__(128, 6)
void qasa_fused(const float* __restrict__ x,
                const float* __restrict__ Win,
                const float* __restrict__ bin,
                const float* __restrict__ qw,
                const float* __restrict__ Wout,
                const float* __restrict__ bout,
                float* __restrict__ out)
{
    __shared__ float  sW[NQ * DIN];        // 32 KB
    __shared__ float4 uc_s[NLAYERS * NQ];  // gate coefficients
    __shared__ float2 cs_s[8][NQ];         // per-row (cos,sin)
    __shared__ float  ev_s[8 * NQ];        // per-row <Z>

    const int tid  = threadIdx.x;
    const int lane = tid & 31;
    const int warp = tid >> 5;
    const int row0 = blockIdx.x * 8;

    // ---- phase 0: gate coefficients (threads 0..31) + Win -> smem --------
    if (tid < NLAYERS * NQ) {
        int lL = tid >> 3, i = tid & 7;
        float th = __ldg(&qw[lL * 16 + i]);       // RX angle
        float ph = __ldg(&qw[lL * 16 + 8 + i]);   // RZ angle
        float s2, c2, sp, cp;
        sincosf(0.5f * th, &s2, &c2);
        sincosf(0.5f * ph, &sp, &cp);
        uc_s[tid] = make_float4(c2 * cp, -c2 * sp, -s2 * sp, -s2 * cp);
    }
    {
        const float4* w4g = reinterpret_cast<const float4*>(Win);
        float4* sW4 = reinterpret_cast<float4*>(sW);
#pragma unroll
        for (int i = 0; i < 16; i++)
            sW4[tid + 128 * i] = __ldg(&w4g[tid + 128 * i]);
    }
    __syncthreads();

    // ---- phase 1: angles for this warp's 2 rows --------------------------
    const float4* sW4 = reinterpret_cast<const float4*>(sW);
#pragma unroll
    for (int rr = 0; rr < 2; rr++) {
        const int row = row0 + warp * 2 + rr;
        const float4* x4 = reinterpret_cast<const float4*>(x + (size_t)row * DIN);
        float4 xv[8];
#pragma unroll
        for (int j = 0; j < 8; j++) xv[j] = __ldcs(&x4[lane + 32 * j]);

        float acc[8];
#pragma unroll
        for (int q = 0; q < NQ; q++) acc[q] = 0.f;
#pragma unroll
        for (int j = 0; j < 8; j++) {
#pragma unroll
            for (int q = 0; q < NQ; q++) {
                float4 wv = sW4[q * 256 + lane + 32 * j];
                acc[q] += xv[j].x * wv.x + xv[j].y * wv.y
                        + xv[j].z * wv.z + xv[j].w * wv.w;
            }
        }
        ull A4[4];
#pragma unroll
        for (int qh = 0; qh < 4; qh++) A4[qh] = pk(acc[2 * qh], acc[2 * qh + 1]);
#pragma unroll
        for (int off = 16; off; off >>= 1)
#pragma unroll
            for (int k = 0; k < 4; k++)
                A4[k] = add2(A4[k], shflx(A4[k], off));

        float h = 0.f;
#pragma unroll
        for (int o = 0; o < 8; o++) {
            if (lane == o) {
                float hx, hy; up2(A4[o >> 1], hx, hy);
                h = (o & 1) ? hy : hx;
            }
        }
        if (lane < 8) {
            float c, s;
            __sincosf(0.5f * (h + __ldg(&bin[lane])), &s, &c);
            cs_s[warp * 2 + rr][lane] = make_float2(c, s);
        }
    }
    __syncwarp();

    // ---- phase 2: circuit (16-lane group g simulates row rib) ------------
    const int l   = lane & 15;
    const int g   = lane >> 4;
    const int rib = warp * 2 + g;

    float C[NQ], S[NQ];
    {
        const float4* cs4 = reinterpret_cast<const float4*>(&cs_s[rib][0]);
#pragma unroll
        for (int j = 0; j < 4; j++) {
            float4 v = cs4[j];
            C[2 * j] = v.x; S[2 * j] = v.y; C[2 * j + 1] = v.z; S[2 * j + 1] = v.w;
        }
    }

    // initial product state: wires 0..3 on lane bits, 4..6 on reg bits, 7 packed
    ull Ar[8], Ai[8];
    {
        float prr = 1.f, pri = 0.f;
#pragma unroll
        for (int w = 0; w < 4; w++) {
            int b = (l >> (3 - w)) & 1;
            float qr = b ? S[w] * S[w] : C[w] * C[w];
            float qi = -S[w] * C[w];
            float nr = prr * qr - pri * qi;
            pri = prr * qi + pri * qr;
            prr = nr;
        }
        float sr[8], si[8];
        sr[0] = prr; si[0] = pri;
        int cnt = 1;
#pragma unroll
        for (int w = 6; w >= 4; w--) {
            float q0r = C[w] * C[w], q1r = S[w] * S[w], qi = -S[w] * C[w];
#pragma unroll
            for (int j = 0; j < 4; j++) {
                if (j < cnt) {
                    float br = sr[j], bi = si[j];
                    sr[j + cnt] = br * q1r - bi * qi;
                    si[j + cnt] = br * qi + bi * q1r;
                    sr[j] = br * q0r - bi * qi;
                    si[j] = br * qi + bi * q0r;
                }
            }
            cnt <<= 1;
        }
        ull qrP = pk(C[7] * C[7], S[7] * S[7]);
        ull qiP = dup2(-S[7] * C[7]);
        ull nqiP = qiP ^ SGN2;
#pragma unroll
        for (int j = 0; j < 8; j++) {
            ull srj = dup2(sr[j]), sij = dup2(si[j]);
            Ar[j] = fma2(nqiP, sij, mul2(qrP, srj));
            Ai[j] = fma2(qiP,  srj, mul2(qrP, sij));
        }
    }

#define G(L, I, MM, RR) { float4 u = uc_s[(L) * 8 + (I)]; \
                          apply_gate8<MM, RR>(Ar, Ai, u, l); }
    // layer 1 (identity frame)
    G(0,0,0x80,0x80) G(0,1,0x40,0x40) G(0,2,0x20,0x20) G(0,3,0x10,0x10)
    G(0,4,0x08,0x08) G(0,5,0x04,0x04) G(0,6,0x02,0x02) G(0,7,0x01,0x01)
    // layer 2
    G(1,0,0xC0,0x80) G(1,1,0x60,0xC0) G(1,2,0x30,0xE0) G(1,3,0x18,0xF0)
    G(1,4,0x0C,0xF8) G(1,5,0x06,0xFC) G(1,6,0x03,0xFE) G(1,7,0x01,0xFF)
    // layer 3
    G(2,0,0xA0,0x80) G(2,1,0x50,0x40) G(2,2,0x28,0xA0) G(2,3,0x14,0x50)
    G(2,4,0x0A,0xA8) G(2,5,0x05,0x54) G(2,6,0x02,0xAA) G(2,7,0x01,0x55)
    // layer 4
    G(3,0,0xF0,0x80) G(3,1,0x78,0xC0) G(3,2,0x3C,0x60) G(3,3,0x1E,0x30)
    G(3,4,0x0F,0x98) G(3,5,0x07,0xCC) G(3,6,0x03,0x66) G(3,7,0x01,0x33)
#undef G

    // probabilities and signed sums
    ull P[8];
#pragma unroll
    for (int j = 0; j < 8; j++) P[j] = fma2(Ai[j], Ai[j], mul2(Ar[j], Ar[j]));

    ull s1[4], d1[4];
#pragma unroll
    for (int k = 0; k < 4; k++) { s1[k] = add2(P[2 * k], P[2 * k + 1]);
                                  d1[k] = sub2(P[2 * k], P[2 * k + 1]); }
    ull s2a = add2(s1[0], s1[1]), s2b = add2(s1[2], s1[3]);
    ull d2a = sub2(s1[0], s1[1]), d2b = sub2(s1[2], s1[3]);
    ull T2  = add2(s2a, s2b);
    ull D4  = sub2(s2a, s2b);
    ull D2  = add2(d2a, d2b);
    ull D1  = add2(add2(d1[0], d1[1]), add2(d1[2], d1[3]));

    float tx, ty; up2(T2, tx, ty);
    float ptot = tx + ty;
    float Ah   = tx - ty;
    float ax, ay; up2(D4, ax, ay); float Aj4 = ax + ay;
    float bx, by; up2(D2, bx, by); float Aj2 = bx + by;
    float cx, cy; up2(D1, cx, cy); float Aj1 = cx + cy;

    float e0 = (l & 8) ? -ptot : ptot;
    float e1 = (l & 4) ? -ptot : ptot;
    float e2 = (l & 2) ? -ptot : ptot;
    float e3 = (l & 1) ? -ptot : ptot;
    float e4 = (l & 8) ? -Aj4 : Aj4;
    float e5 = (l & 4) ? -Aj2 : Aj2;
    float e6 = (l & 2) ? -Aj1 : Aj1;
    float e7 = (l & 1) ? -Ah  : Ah;

    ull E[4] = { pk(e0, e1), pk(e2, e3), pk(e4, e5), pk(e6, e7) };
#pragma unroll
    for (int off = 8; off; off >>= 1)
#pragma unroll
        for (int k = 0; k < 4; k++)
            E[k] = add2(E[k], shflx(E[k], off));

    float myev = 0.f;
#pragma unroll
    for (int o = 0; o < 8; o++) {
        if (l == o) {
            float vx, vy; up2(E[o >> 1], vx, vy);
            myev = (o & 1) ? vy : vx;
        }
    }
    if (l < 8)
        ev_s[rib * NQ + l] = myev;
    __syncthreads();

    // ---- phase 3: out = ev @ Wout^T + bout (two halves, 32 weight regs) --
    const float4* wo4 = reinterpret_cast<const float4*>(Wout);  // [DOUT][2]
    float4* out4 = reinterpret_cast<float4*>(out);
#pragma unroll
    for (int half = 0; half < 2; half++) {
        ull w[2][8], bo[2];
#pragma unroll
        for (int pp = 0; pp < 2; pp++) {
            int c0p = half * 512 + tid * 4 + pp * 2;
            float4 wa0 = __ldg(&wo4[c0p * 2 + 0]);
            float4 wa1 = __ldg(&wo4[c0p * 2 + 1]);
            float4 wb0 = __ldg(&wo4[(c0p + 1) * 2 + 0]);
            float4 wb1 = __ldg(&wo4[(c0p + 1) * 2 + 1]);
            w[pp][0] = pk(wa0.x, wb0.x); w[pp][1] = pk(wa0.y, wb0.y);
            w[pp][2] = pk(wa0.z, wb0.z); w[pp][3] = pk(wa0.w, wb0.w);
            w[pp][4] = pk(wa1.x, wb1.x); w[pp][5] = pk(wa1.y, wb1.y);
            w[pp][6] = pk(wa1.z, wb1.z); w[pp][7] = pk(wa1.w, wb1.w);
            bo[pp] = pk(__ldg(&bout[c0p]), __ldg(&bout[c0p + 1]));
        }
#pragma unroll
        for (int r = 0; r < 8; r++) {
            ull acc0 = bo[0], acc1 = bo[1];
#pragma unroll
            for (int q = 0; q < NQ; q++) {
                ull eq = dup2(ev_s[r * NQ + q]);
                acc0 = fma2(w[0][q], eq, acc0);
                acc1 = fma2(w[1][q], eq, acc1);
            }
            float4 o;
            up2(acc0, o.x, o.y); up2(acc1, o.z, o.w);
            out4[(size_t)(row0 + r) * (DOUT / 4) + half * 128 + tid] = o;
        }
    }
}

extern "C" void kernel_launch(void* const* d_in, const int* in_sizes, int n_in,
                              void* d_out, int out_size) {
    const float* x    = (const float*)d_in[0];
    const float* Win  = (const float*)d_in[1];
    const float* bin  = (const float*)d_in[2];
    const float* qw   = (const float*)d_in[3];
    const float* Wout = (const float*)d_in[4];
    const float* bout = (const float*)d_in[5];
    float* out = (float*)d_out;

    int B = in_sizes[0] / DIN;            // 8192
    qasa_fused<<<B / 8, 128>>>(x, Win, bin, qw, Wout, bout, out);
}

// round 12
// speedup vs baseline: 1.5765x; 1.5765x over previous
#include <cuda_runtime.h>
#include <cstdint>

#define NQ      8
#define NLAYERS 4
#define DIN     1024
#define DOUT    1024
#define BMAX    8192

using ull = unsigned long long;
#define SGN2 0x8000000080000000ULL

// ---------------- packed f32x2 helpers (Blackwell dual-FP32) ----------------
__device__ __forceinline__ ull pk(float x, float y) {
    ull r; asm("mov.b64 %0,{%1,%2};" : "=l"(r) : "f"(x), "f"(y)); return r;
}
__device__ __forceinline__ void up2(ull a, float& x, float& y) {
    asm("mov.b64 {%0,%1},%2;" : "=f"(x), "=f"(y) : "l"(a));
}
__device__ __forceinline__ ull dup2(float x) { return pk(x, x); }
__device__ __forceinline__ ull fma2(ull a, ull b, ull c) {
    ull d; asm("fma.rn.f32x2 %0,%1,%2,%3;" : "=l"(d) : "l"(a), "l"(b), "l"(c)); return d;
}
__device__ __forceinline__ ull mul2(ull a, ull b) {
    ull d; asm("mul.rn.f32x2 %0,%1,%2;" : "=l"(d) : "l"(a), "l"(b)); return d;
}
__device__ __forceinline__ ull add2(ull a, ull b) {
    ull d; asm("add.rn.f32x2 %0,%1,%2;" : "=l"(d) : "l"(a), "l"(b)); return d;
}
__device__ __forceinline__ ull sub2(ull a, ull b) { return add2(a, b ^ SGN2); }
__device__ __forceinline__ ull swp(ull a) { float x, y; up2(a, x, y); return pk(y, x); }
__device__ __forceinline__ ull shflx(ull a, int m) {
    float x, y; up2(a, x, y);
    x = __shfl_xor_sync(0xffffffffu, x, m);
    y = __shfl_xor_sync(0xffffffffu, y, m);
    return pk(x, y);
}

// ---------------- device buffers / gate coefficients ----------------
// Per gate only u00,u01 needed (u11=conj(u00), u10=-conj(u01)).
__device__ float4 g_ucoef[NLAYERS * NQ];    // {u00r,u00i,u01r,u01i}
__device__ float2 g_cs[BMAX * NQ];          // (cos,sin) per row per wire

// ================= K1: angles = x @ Win^T + bin ; store (cos,sin) =========
__global__ __launch_bounds__(128)
void k1_angles(const float* __restrict__ x,
               const float* __restrict__ Win,
               const float* __restrict__ bin,
               const float* __restrict__ qw)
{
    __shared__ float sW[NQ * DIN];     // 32 KB

    const int tid  = threadIdx.x;
    const int lane = tid & 31;
    const int warp = tid >> 5;
    const int row0 = blockIdx.x * 8 + warp * 2;

    const float4* xr0 = reinterpret_cast<const float4*>(x + (size_t)row0 * DIN);
    const float4* xr1 = reinterpret_cast<const float4*>(x + (size_t)(row0 + 1) * DIN);
    float4 xa[8], xb[8];
#pragma unroll
    for (int j = 0; j < 8; j++) xa[j] = __ldcs(&xr0[lane + 32 * j]);
#pragma unroll
    for (int j = 0; j < 8; j++) xb[j] = __ldcs(&xr1[lane + 32 * j]);

    {
        const float4* w4g = reinterpret_cast<const float4*>(Win);
        float4* sW4 = reinterpret_cast<float4*>(sW);
#pragma unroll
        for (int i = 0; i < 16; i++)
            sW4[tid + 128 * i] = __ldg(&w4g[tid + 128 * i]);
    }
    __syncthreads();

    float acc[2][8];
#pragma unroll
    for (int r = 0; r < 2; r++)
#pragma unroll
        for (int q = 0; q < NQ; q++) acc[r][q] = 0.f;

    const float4* sW4 = reinterpret_cast<const float4*>(sW);
#pragma unroll
    for (int j = 0; j < 8; j++) {
#pragma unroll
        for (int q = 0; q < NQ; q++) {
            float4 wv = sW4[q * 256 + lane + 32 * j];
            acc[0][q] += xa[j].x * wv.x + xa[j].y * wv.y
                       + xa[j].z * wv.z + xa[j].w * wv.w;
            acc[1][q] += xb[j].x * wv.x + xb[j].y * wv.y
                       + xb[j].z * wv.z + xb[j].w * wv.w;
        }
    }

    ull A8[8];
#pragma unroll
    for (int r = 0; r < 2; r++)
#pragma unroll
        for (int qh = 0; qh < 4; qh++)
            A8[r * 4 + qh] = pk(acc[r][2 * qh], acc[r][2 * qh + 1]);
#pragma unroll
    for (int off = 16; off; off >>= 1)
#pragma unroll
        for (int k = 0; k < 8; k++)
            A8[k] = add2(A8[k], shflx(A8[k], off));

    float h = 0.f;
#pragma unroll
    for (int o = 0; o < 16; o++) {
        if (lane == o) {
            float hx, hy;
            up2(A8[(o >> 3) * 4 + ((o & 7) >> 1)], hx, hy);
            h = (o & 1) ? hy : hx;
        }
    }
    if (lane < 16) {
        const int rr = lane >> 3;
        const int qq = lane & 7;
        float c, s;
        __sincosf(0.5f * (h + __ldg(&bin[qq])), &s, &c);
        g_cs[(size_t)(row0 + rr) * NQ + qq] = make_float2(c, s);
    }

    if (blockIdx.x == 0 && tid < NLAYERS * NQ) {
        int t = tid;
        int l = t >> 3, i = t & 7;
        float th = qw[l * 16 + i];        // weights[l][0][i] (RX)
        float ph = qw[l * 16 + 8 + i];    // weights[l][1][i] (RZ)
        float s2, c2, sp, cp;
        sincosf(0.5f * th, &s2, &c2);
        sincosf(0.5f * ph, &sp, &cp);
        g_ucoef[t] = make_float4(c2 * cp, -c2 * sp, -s2 * sp, -s2 * cp);
    }
}

// ================= K23: circuit (16 lanes/row, 16 amps/lane) + output GEMM ==
// Warp = 2 groups of 16 lanes; group g simulates one row. Physical amp
// p[7:0]: bits 7..4 = group-lane l[3:0], bits 3..0 = local r. Packed pairs
// over bit0: reg j = r>>1 (8 ull per component).
// Gate mask M, parity row R: new[p] = d(b)*old[p] + o(b)*old[p^M], b=popc(p&R).
// Conjugate structure (u11=conj u00, u10=-conj u01): parity flips sign of
// (di, or) only.
template<int M, int R>
__device__ __forceinline__ void apply_gate8(ull* Ar, ull* Ai, float4 u, int l)
{
    constexpr int lm    = M >> 4;
    constexpr int loj   = (M & 15) >> 1;
    constexpr int lo0   = M & 1;
    constexpr int Rlane = R >> 4;
    constexpr int Rj    = (R & 15) >> 1;
    constexpr int R0    = R & 1;

    const bool pl = (__popc(l & Rlane) & 1) != 0;

    const ull drP  = dup2(u.x);
    const ull oiP  = dup2(u.w);
    const ull noiP = oiP ^ SGN2;
    ull diB = (R0 == 0) ? dup2(u.y) : pk(u.y, -u.y);
    ull orB = (R0 == 0) ? dup2(u.z) : pk(u.z, -u.z);
    if (pl) { diB ^= SGN2; orB ^= SGN2; }
    const ull diN = diB ^ SGN2, orN = orB ^ SGN2;

#define GUPD(jj, PR, PI)                                                        \
    {   const bool sj = (__popc((jj) & Rj) & 1) != 0;                           \
        const ull dij = sj ? diN : diB, ndij = sj ? diB : diN;                  \
        const ull orj = sj ? orN : orB;                                         \
        ull mr = Ar[jj], mi = Ai[jj];                                           \
        Ar[jj] = fma2(orj, PR, fma2(noiP, PI, fma2(ndij, mi, mul2(drP, mr))));  \
        Ai[jj] = fma2(oiP, PR, fma2(orj,  PI, fma2(dij,  mr, mul2(drP, mi)))); }

    if (loj == 0) {
#pragma unroll
        for (int j = 0; j < 8; j++) {
            ull Pr = Ar[j], Pi_ = Ai[j];
            if (lo0) { Pr = swp(Pr); Pi_ = swp(Pi_); }
            if (lm)  { Pr = shflx(Pr, lm); Pi_ = shflx(Pi_, lm); }
            GUPD(j, Pr, Pi_)
        }
    } else {
#pragma unroll
        for (int j = 0; j < 8; j++) {
            const int j2 = j ^ loj;
            if (j < j2) {
                ull Par = Ar[j2], Pai = Ai[j2];
                ull Pbr = Ar[j],  Pbi = Ai[j];
                if (lo0) { Par = swp(Par); Pai = swp(Pai); Pbr = swp(Pbr); Pbi = swp(Pbi); }
                if (lm)  { Par = shflx(Par, lm); Pai = shflx(Pai, lm);
                           Pbr = shflx(Pbr, lm); Pbi = shflx(Pbi, lm); }
                GUPD(j,  Par, Pai)
                GUPD(j2, Pbr, Pbi)
            }
        }
    }
#undef GUPD
}

__global__ __launch_bounds__(128, 6)
void k23_circuit_out(const float* __restrict__ Wout,
                     const float* __restrict__ bout,
                     float* __restrict__ out)
{
    const int tid  = threadIdx.x;
    const int lane = tid & 31;
    const int warp = tid >> 5;
    const int l    = lane & 15;        // lane within 16-lane group
    const int g    = lane >> 4;        // group = row within warp
    const int row0 = blockIdx.x * 8;
    const int rib  = warp * 2 + g;     // row in block (0..7)
    const int row  = row0 + rib;

    __shared__ float ev_s[8 * NQ];

    float C[NQ], S[NQ];
    {
        const float4* cs4 = reinterpret_cast<const float4*>(&g_cs[(size_t)row * NQ]);
#pragma unroll
        for (int j = 0; j < 4; j++) {
            float4 v = __ldg(&cs4[j]);
            C[2 * j] = v.x; S[2 * j] = v.y; C[2 * j + 1] = v.z; S[2 * j + 1] = v.w;
        }
    }

    // initial product state: lane wires 0..3 (l bits 3..0), wires 4..6 on
    // reg bits j[2..0], wire 7 on packed half.
    ull Ar[8], Ai[8];
    {
        float prr = 1.f, pri = 0.f;
#pragma unroll
        for (int w = 0; w < 4; w++) {
            int b = (l >> (3 - w)) & 1;
            float qr = b ? S[w] * S[w] : C[w] * C[w];
            float qi = -S[w] * C[w];
            float nr = prr * qr - pri * qi;
            pri = prr * qi + pri * qr;
            prr = nr;
        }
        float sr[8], si[8];
        sr[0] = prr; si[0] = pri;
        int cnt = 1;
#pragma unroll
        for (int w = 6; w >= 4; w--) {      // wire w -> j bit (6-w)
            float q0r = C[w] * C[w], q1r = S[w] * S[w], qi = -S[w] * C[w];
#pragma unroll
            for (int j = 0; j < 4; j++) {
                if (j < cnt) {
                    float br = sr[j], bi = si[j];
                    sr[j + cnt] = br * q1r - bi * qi;
                    si[j + cnt] = br * qi + bi * q1r;
                    sr[j] = br * q0r - bi * qi;
                    si[j] = br * qi + bi * q0r;
                }
            }
            cnt <<= 1;
        }
        // wire 7 on packed half
        ull qrP = pk(C[7] * C[7], S[7] * S[7]);
        ull qiP = dup2(-S[7] * C[7]);
        ull nqiP = qiP ^ SGN2;
#pragma unroll
        for (int j = 0; j < 8; j++) {
            ull srj = dup2(sr[j]), sij = dup2(si[j]);
            Ar[j] = fma2(nqiP, sij, mul2(qrP, srj));
            Ai[j] = fma2(qiP,  srj, mul2(qrP, sij));
        }
    }

#define G(L, I, MM, RR) { float4 u = __ldg(&g_ucoef[(L) * 8 + (I)]); \
                          apply_gate8<MM, RR>(Ar, Ai, u, l); }
    // layer 1 (identity frame)
    G(0,0,0x80,0x80) G(0,1,0x40,0x40) G(0,2,0x20,0x20) G(0,3,0x10,0x10)
    G(0,4,0x08,0x08) G(0,5,0x04,0x04) G(0,6,0x02,0x02) G(0,7,0x01,0x01)
    // layer 2
    G(1,0,0xC0,0x80) G(1,1,0x60,0xC0) G(1,2,0x30,0xE0) G(1,3,0x18,0xF0)
    G(1,4,0x0C,0xF8) G(1,5,0x06,0xFC) G(1,6,0x03,0xFE) G(1,7,0x01,0xFF)
    // layer 3
    G(2,0,0xA0,0x80) G(2,1,0x50,0x40) G(2,2,0x28,0xA0) G(2,3,0x14,0x50)
    G(2,4,0x0A,0xA8) G(2,5,0x05,0x54) G(2,6,0x02,0xAA) G(2,7,0x01,0x55)
    // layer 4
    G(3,0,0xF0,0x80) G(3,1,0x78,0xC0) G(3,2,0x3C,0x60) G(3,3,0x1E,0x30)
    G(3,4,0x0F,0x98) G(3,5,0x07,0xCC) G(3,6,0x03,0x66) G(3,7,0x01,0x33)
#undef G

    // probabilities and signed local sums
    ull P[8];
#pragma unroll
    for (int j = 0; j < 8; j++) P[j] = fma2(Ai[j], Ai[j], mul2(Ar[j], Ar[j]));

    ull s1[4], d1[4];
#pragma unroll
    for (int k = 0; k < 4; k++) { s1[k] = add2(P[2 * k], P[2 * k + 1]);
                                  d1[k] = sub2(P[2 * k], P[2 * k + 1]); }
    ull s2a = add2(s1[0], s1[1]), s2b = add2(s1[2], s1[3]);
    ull d2a = sub2(s1[0], s1[1]), d2b = sub2(s1[2], s1[3]);
    ull T2  = add2(s2a, s2b);                 // all +
    ull D4  = sub2(s2a, s2b);                 // sign: j bit2 (wire4)
    ull D2  = add2(d2a, d2b);                 // sign: j bit1 (wire5)
    ull D1  = add2(add2(d1[0], d1[1]), add2(d1[2], d1[3]));  // j bit0 (wire6)

    float tx, ty; up2(T2, tx, ty);
    float ptot = tx + ty;
    float Ah   = tx - ty;                     // sign: packed half (wire7)
    float ax, ay; up2(D4, ax, ay); float Aj4 = ax + ay;
    float bx, by; up2(D2, bx, by); float Aj2 = bx + by;
    float cx, cy; up2(D1, cx, cy); float Aj1 = cx + cy;

    // ev sign rows Rf = [0x80,0x40,0x20,0x10,0x88,0x44,0x22,0x11]
    float e0 = (l & 8) ? -ptot : ptot;
    float e1 = (l & 4) ? -ptot : ptot;
    float e2 = (l & 2) ? -ptot : ptot;
    float e3 = (l & 1) ? -ptot : ptot;
    float e4 = (l & 8) ? -Aj4 : Aj4;
    float e5 = (l & 4) ? -Aj2 : Aj2;
    float e6 = (l & 2) ? -Aj1 : Aj1;
    float e7 = (l & 1) ? -Ah  : Ah;

    ull E[4] = { pk(e0, e1), pk(e2, e3), pk(e4, e5), pk(e6, e7) };
#pragma unroll
    for (int off = 8; off; off >>= 1)
#pragma unroll
        for (int k = 0; k < 4; k++)
            E[k] = add2(E[k], shflx(E[k], off));

    float myev = 0.f;
#pragma unroll
    for (int o = 0; o < 8; o++) {
        if (l == o) {
            float vx, vy; up2(E[o >> 1], vx, vy);
            myev = (o & 1) ? vy : vx;
        }
    }
    if (l < 8)
        ev_s[rib * NQ + l] = myev;
    __syncthreads();

    // ---------------- Phase B: out = ev @ Wout^T + bout (two halves) ------
    const float4* wo4 = reinterpret_cast<const float4*>(Wout);  // [DOUT][2]
    float4* out4 = reinterpret_cast<float4*>(out);
#pragma unroll
    for (int half = 0; half < 2; half++) {
        ull w[2][8], bo[2];
#pragma unroll
        for (int pp = 0; pp < 2; pp++) {
            int c0p = half * 512 + tid * 4 + pp * 2;
            float4 wa0 = __ldg(&wo4[c0p * 2 + 0]);
            float4 wa1 = __ldg(&wo4[c0p * 2 + 1]);
            float4 wb0 = __ldg(&wo4[(c0p + 1) * 2 + 0]);
            float4 wb1 = __ldg(&wo4[(c0p + 1) * 2 + 1]);
            w[pp][0] = pk(wa0.x, wb0.x); w[pp][1] = pk(wa0.y, wb0.y);
            w[pp][2] = pk(wa0.z, wb0.z); w[pp][3] = pk(wa0.w, wb0.w);
            w[pp][4] = pk(wa1.x, wb1.x); w[pp][5] = pk(wa1.y, wb1.y);
            w[pp][6] = pk(wa1.z, wb1.z); w[pp][7] = pk(wa1.w, wb1.w);
            bo[pp] = pk(__ldg(&bout[c0p]), __ldg(&bout[c0p + 1]));
        }
#pragma unroll
        for (int r = 0; r < 8; r++) {
            ull acc0 = bo[0], acc1 = bo[1];
#pragma unroll
            for (int q = 0; q < NQ; q++) {
                ull eq = dup2(ev_s[r * NQ + q]);
                acc0 = fma2(w[0][q], eq, acc0);
                acc1 = fma2(w[1][q], eq, acc1);
            }
            float4 o;
            up2(acc0, o.x, o.y); up2(acc1, o.z, o.w);
            out4[(size_t)(row0 + r) * (DOUT / 4) + half * 128 + tid] = o;
        }
    }
}

extern "C" void kernel_launch(void* const* d_in, const int* in_sizes, int n_in,
                              void* d_out, int out_size) {
    const float* x    = (const float*)d_in[0];
    const float* Win  = (const float*)d_in[1];
    const float* bin  = (const float*)d_in[2];
    const float* qw   = (const float*)d_in[3];
    const float* Wout = (const float*)d_in[4];
    const float* bout = (const float*)d_in[5];
    float* out = (float*)d_out;

    int B = in_sizes[0] / DIN;            // 8192
    k1_angles<<<B / 8, 128>>>(x, Win, bin, qw);
    k23_circuit_out<<<B / 8, 128>>>(Wout, bout, out);
}

// round 14
// speedup vs baseline: 1.7718x; 1.1238x over previous
#include <cuda_runtime.h>
#include <cstdint>

#define NQ      8
#define NLAYERS 4
#define DIN     1024
#define DOUT    1024
#define BMAX    8192

using ull = unsigned long long;
#define SGN2 0x8000000080000000ULL

// ---------------- packed f32x2 helpers (Blackwell dual-FP32) ----------------
__device__ __forceinline__ ull pk(float x, float y) {
    ull r; asm("mov.b64 %0,{%1,%2};" : "=l"(r) : "f"(x), "f"(y)); return r;
}
__device__ __forceinline__ void up2(ull a, float& x, float& y) {
    asm("mov.b64 {%0,%1},%2;" : "=f"(x), "=f"(y) : "l"(a));
}
__device__ __forceinline__ ull dup2(float x) { return pk(x, x); }
__device__ __forceinline__ ull fma2(ull a, ull b, ull c) {
    ull d; asm("fma.rn.f32x2 %0,%1,%2,%3;" : "=l"(d) : "l"(a), "l"(b), "l"(c)); return d;
}
__device__ __forceinline__ ull mul2(ull a, ull b) {
    ull d; asm("mul.rn.f32x2 %0,%1,%2;" : "=l"(d) : "l"(a), "l"(b)); return d;
}
__device__ __forceinline__ ull add2(ull a, ull b) {
    ull d; asm("add.rn.f32x2 %0,%1,%2;" : "=l"(d) : "l"(a), "l"(b)); return d;
}
__device__ __forceinline__ ull sub2(ull a, ull b) { return add2(a, b ^ SGN2); }
__device__ __forceinline__ ull swp(ull a) { float x, y; up2(a, x, y); return pk(y, x); }
__device__ __forceinline__ ull shflx(ull a, int m) {
    float x, y; up2(a, x, y);
    x = __shfl_xor_sync(0xffffffffu, x, m);
    y = __shfl_xor_sync(0xffffffffu, y, m);
    return pk(x, y);
}

// ---------------- device buffers / gate coefficients ----------------
// Per gate only u00,u01 needed (u11=conj(u00), u10=-conj(u01)).
__device__ float4 g_ucoef[NLAYERS * NQ];    // {u00r,u00i,u01r,u01i}
__device__ float2 g_cs[BMAX * NQ];          // (cos,sin) per row per wire

// ================= K1: angles = x @ Win^T + bin ; store (cos,sin) =========
__global__ __launch_bounds__(128)
void k1_angles(const float* __restrict__ x,
               const float* __restrict__ Win,
               const float* __restrict__ bin,
               const float* __restrict__ qw)
{
    __shared__ float sW[NQ * DIN];     // 32 KB

    const int tid  = threadIdx.x;
    const int lane = tid & 31;
    const int warp = tid >> 5;
    const int row0 = blockIdx.x * 8 + warp * 2;

    const float4* xr0 = reinterpret_cast<const float4*>(x + (size_t)row0 * DIN);
    const float4* xr1 = reinterpret_cast<const float4*>(x + (size_t)(row0 + 1) * DIN);
    float4 xa[8], xb[8];
#pragma unroll
    for (int j = 0; j < 8; j++) xa[j] = __ldcs(&xr0[lane + 32 * j]);
#pragma unroll
    for (int j = 0; j < 8; j++) xb[j] = __ldcs(&xr1[lane + 32 * j]);

    {
        const float4* w4g = reinterpret_cast<const float4*>(Win);
        float4* sW4 = reinterpret_cast<float4*>(sW);
#pragma unroll
        for (int i = 0; i < 16; i++)
            sW4[tid + 128 * i] = __ldg(&w4g[tid + 128 * i]);
    }
    __syncthreads();

    float acc[2][8];
#pragma unroll
    for (int r = 0; r < 2; r++)
#pragma unroll
        for (int q = 0; q < NQ; q++) acc[r][q] = 0.f;

    const float4* sW4 = reinterpret_cast<const float4*>(sW);
#pragma unroll
    for (int j = 0; j < 8; j++) {
#pragma unroll
        for (int q = 0; q < NQ; q++) {
            float4 wv = sW4[q * 256 + lane + 32 * j];
            acc[0][q] += xa[j].x * wv.x + xa[j].y * wv.y
                       + xa[j].z * wv.z + xa[j].w * wv.w;
            acc[1][q] += xb[j].x * wv.x + xb[j].y * wv.y
                       + xb[j].z * wv.z + xb[j].w * wv.w;
        }
    }

    ull A8[8];
#pragma unroll
    for (int r = 0; r < 2; r++)
#pragma unroll
        for (int qh = 0; qh < 4; qh++)
            A8[r * 4 + qh] = pk(acc[r][2 * qh], acc[r][2 * qh + 1]);
#pragma unroll
    for (int off = 16; off; off >>= 1)
#pragma unroll
        for (int k = 0; k < 8; k++)
            A8[k] = add2(A8[k], shflx(A8[k], off));

    float h = 0.f;
#pragma unroll
    for (int o = 0; o < 16; o++) {
        if (lane == o) {
            float hx, hy;
            up2(A8[(o >> 3) * 4 + ((o & 7) >> 1)], hx, hy);
            h = (o & 1) ? hy : hx;
        }
    }
    if (lane < 16) {
        const int rr = lane >> 3;
        const int qq = lane & 7;
        float c, s;
        __sincosf(0.5f * (h + __ldg(&bin[qq])), &s, &c);
        g_cs[(size_t)(row0 + rr) * NQ + qq] = make_float2(c, s);
    }

    if (blockIdx.x == 0 && tid < NLAYERS * NQ) {
        int t = tid;
        int l = t >> 3, i = t & 7;
        float th = qw[l * 16 + i];        // weights[l][0][i] (RX)
        float ph = qw[l * 16 + 8 + i];    // weights[l][1][i] (RZ)
        float s2, c2, sp, cp;
        sincosf(0.5f * th, &s2, &c2);
        sincosf(0.5f * ph, &sp, &cp);
        g_ucoef[t] = make_float4(c2 * cp, -c2 * sp, -s2 * sp, -s2 * cp);
    }
}

// ================= K23: circuit (16 lanes/row, 16 amps/lane) + output GEMM ==
// Warp = 2 groups of 16 lanes; group g simulates one row. Physical amp
// p[7:0]: bits 7..4 = group-lane l[3:0], bits 3..0 = local r. Packed pairs
// over bit0: reg j = r>>1 (8 ull per component).
// Gate mask M, parity row R: new[p] = d(b)*old[p] + o(b)*old[p^M], b=popc(p&R).
// Conjugate structure (u11=conj u00, u10=-conj u01): parity flips sign of
// (di, or) only.
template<int M, int R>
__device__ __forceinline__ void apply_gate8(ull* Ar, ull* Ai, float4 u, int l)
{
    constexpr int lm    = M >> 4;
    constexpr int loj   = (M & 15) >> 1;
    constexpr int lo0   = M & 1;
    constexpr int Rlane = R >> 4;
    constexpr int Rj    = (R & 15) >> 1;
    constexpr int R0    = R & 1;

    const bool pl = (__popc(l & Rlane) & 1) != 0;

    const ull drP  = dup2(u.x);
    const ull oiP  = dup2(u.w);
    const ull noiP = oiP ^ SGN2;
    ull diB = (R0 == 0) ? dup2(u.y) : pk(u.y, -u.y);
    ull orB = (R0 == 0) ? dup2(u.z) : pk(u.z, -u.z);
    if (pl) { diB ^= SGN2; orB ^= SGN2; }
    const ull diN = diB ^ SGN2, orN = orB ^ SGN2;

#define GUPD(jj, PR, PI)                                                        \
    {   const bool sj = (__popc((jj) & Rj) & 1) != 0;                           \
        const ull dij = sj ? diN : diB, ndij = sj ? diB : diN;                  \
        const ull orj = sj ? orN : orB;                                         \
        ull mr = Ar[jj], mi = Ai[jj];                                           \
        Ar[jj] = fma2(orj, PR, fma2(noiP, PI, fma2(ndij, mi, mul2(drP, mr))));  \
        Ai[jj] = fma2(oiP, PR, fma2(orj,  PI, fma2(dij,  mr, mul2(drP, mi)))); }

    if (loj == 0) {
#pragma unroll
        for (int j = 0; j < 8; j++) {
            ull Pr = Ar[j], Pi_ = Ai[j];
            if (lo0) { Pr = swp(Pr); Pi_ = swp(Pi_); }
            if (lm)  { Pr = shflx(Pr, lm); Pi_ = shflx(Pi_, lm); }
            GUPD(j, Pr, Pi_)
        }
    } else {
#pragma unroll
        for (int j = 0; j < 8; j++) {
            const int j2 = j ^ loj;
            if (j < j2) {
                ull Par = Ar[j2], Pai = Ai[j2];
                ull Pbr = Ar[j],  Pbi = Ai[j];
                if (lo0) { Par = swp(Par); Pai = swp(Pai); Pbr = swp(Pbr); Pbi = swp(Pbi); }
                if (lm)  { Par = shflx(Par, lm); Pai = shflx(Pai, lm);
                           Pbr = shflx(Pbr, lm); Pbi = shflx(Pbi, lm); }
                GUPD(j,  Par, Pai)
                GUPD(j2, Pbr, Pbi)
            }
        }
    }
#undef GUPD
}

__global__ __launch_bounds__(128, 6)
void k23_circuit_out(const float* __restrict__ Wout,
                     const float* __restrict__ bout,
                     float* __restrict__ out)
{
    const int tid  = threadIdx.x;
    const int lane = tid & 31;
    const int warp = tid >> 5;
    const int l    = lane & 15;        // lane within 16-lane group
    const int g    = lane >> 4;        // group = row within warp
    const int row0 = blockIdx.x * 8;
    const int rib  = warp * 2 + g;     // row in block (0..7)
    const int row  = row0 + rib;

    __shared__ float ev_s[8 * NQ];

    float C[NQ], S[NQ];
    {
        const float4* cs4 = reinterpret_cast<const float4*>(&g_cs[(size_t)row * NQ]);
#pragma unroll
        for (int j = 0; j < 4; j++) {
            float4 v = __ldg(&cs4[j]);
            C[2 * j] = v.x; S[2 * j] = v.y; C[2 * j + 1] = v.z; S[2 * j + 1] = v.w;
        }
    }

    // initial product state: lane wires 0..3 (l bits 3..0), wires 4..6 on
    // reg bits j[2..0], wire 7 on packed half.
    ull Ar[8], Ai[8];
    {
        float prr = 1.f, pri = 0.f;
#pragma unroll
        for (int w = 0; w < 4; w++) {
            int b = (l >> (3 - w)) & 1;
            float qr = b ? S[w] * S[w] : C[w] * C[w];
            float qi = -S[w] * C[w];
            float nr = prr * qr - pri * qi;
            pri = prr * qi + pri * qr;
            prr = nr;
        }
        float sr[8], si[8];
        sr[0] = prr; si[0] = pri;
        int cnt = 1;
#pragma unroll
        for (int w = 6; w >= 4; w--) {      // wire w -> j bit (6-w)
            float q0r = C[w] * C[w], q1r = S[w] * S[w], qi = -S[w] * C[w];
#pragma unroll
            for (int j = 0; j < 4; j++) {
                if (j < cnt) {
                    float br = sr[j], bi = si[j];
                    sr[j + cnt] = br * q1r - bi * qi;
                    si[j + cnt] = br * qi + bi * q1r;
                    sr[j] = br * q0r - bi * qi;
                    si[j] = br * qi + bi * q0r;
                }
            }
            cnt <<= 1;
        }
        // wire 7 on packed half
        ull qrP = pk(C[7] * C[7], S[7] * S[7]);
        ull qiP = dup2(-S[7] * C[7]);
        ull nqiP = qiP ^ SGN2;
#pragma unroll
        for (int j = 0; j < 8; j++) {
            ull srj = dup2(sr[j]), sij = dup2(si[j]);
            Ar[j] = fma2(nqiP, sij, mul2(qrP, srj));
            Ai[j] = fma2(qiP,  srj, mul2(qrP, sij));
        }
    }

#define G(L, I, MM, RR) { float4 u = __ldg(&g_ucoef[(L) * 8 + (I)]); \
                          apply_gate8<MM, RR>(Ar, Ai, u, l); }
    // layer 1 (identity frame)
    G(0,0,0x80,0x80) G(0,1,0x40,0x40) G(0,2,0x20,0x20) G(0,3,0x10,0x10)
    G(0,4,0x08,0x08) G(0,5,0x04,0x04) G(0,6,0x02,0x02) G(0,7,0x01,0x01)
    // layer 2
    G(1,0,0xC0,0x80) G(1,1,0x60,0xC0) G(1,2,0x30,0xE0) G(1,3,0x18,0xF0)
    G(1,4,0x0C,0xF8) G(1,5,0x06,0xFC) G(1,6,0x03,0xFE) G(1,7,0x01,0xFF)
    // layer 3
    G(2,0,0xA0,0x80) G(2,1,0x50,0x40) G(2,2,0x28,0xA0) G(2,3,0x14,0x50)
    G(2,4,0x0A,0xA8) G(2,5,0x05,0x54) G(2,6,0x02,0xAA) G(2,7,0x01,0x55)
    // layer 4
    G(3,0,0xF0,0x80) G(3,1,0x78,0xC0) G(3,2,0x3C,0x60) G(3,3,0x1E,0x30)
    G(3,4,0x0F,0x98) G(3,5,0x07,0xCC) G(3,6,0x03,0x66) G(3,7,0x01,0x33)
#undef G

    // probabilities and signed local sums
    ull P[8];
#pragma unroll
    for (int j = 0; j < 8; j++) P[j] = fma2(Ai[j], Ai[j], mul2(Ar[j], Ar[j]));

    ull s1[4], d1[4];
#pragma unroll
    for (int k = 0; k < 4; k++) { s1[k] = add2(P[2 * k], P[2 * k + 1]);
                                  d1[k] = sub2(P[2 * k], P[2 * k + 1]); }
    ull s2a = add2(s1[0], s1[1]), s2b = add2(s1[2], s1[3]);
    ull d2a = sub2(s1[0], s1[1]), d2b = sub2(s1[2], s1[3]);
    ull T2  = add2(s2a, s2b);                 // all +
    ull D4  = sub2(s2a, s2b);                 // sign: j bit2 (wire4)
    ull D2  = add2(d2a, d2b);                 // sign: j bit1 (wire5)
    ull D1  = add2(add2(d1[0], d1[1]), add2(d1[2], d1[3]));  // j bit0 (wire6)

    float tx, ty; up2(T2, tx, ty);
    float ptot = tx + ty;
    float Ah   = tx - ty;                     // sign: packed half (wire7)
    float ax, ay; up2(D4, ax, ay); float Aj4 = ax + ay;
    float bx, by; up2(D2, bx, by); float Aj2 = bx + by;
    float cx, cy; up2(D1, cx, cy); float Aj1 = cx + cy;

    // ev sign rows Rf = [0x80,0x40,0x20,0x10,0x88,0x44,0x22,0x11]
    float e0 = (l & 8) ? -ptot : ptot;
    float e1 = (l & 4) ? -ptot : ptot;
    float e2 = (l & 2) ? -ptot : ptot;
    float e3 = (l & 1) ? -ptot : ptot;
    float e4 = (l & 8) ? -Aj4 : Aj4;
    float e5 = (l & 4) ? -Aj2 : Aj2;
    float e6 = (l & 2) ? -Aj1 : Aj1;
    float e7 = (l & 1) ? -Ah  : Ah;

    ull E[4] = { pk(e0, e1), pk(e2, e3), pk(e4, e5), pk(e6, e7) };
#pragma unroll
    for (int off = 8; off; off >>= 1)
#pragma unroll
        for (int k = 0; k < 4; k++)
            E[k] = add2(E[k], shflx(E[k], off));

    float myev = 0.f;
#pragma unroll
    for (int o = 0; o < 8; o++) {
        if (l == o) {
            float vx, vy; up2(E[o >> 1], vx, vy);
            myev = (o & 1) ? vy : vx;
        }
    }
    if (l < 8)
        ev_s[rib * NQ + l] = myev;
    __syncthreads();

    // ---------------- Phase B: out = ev @ Wout^T + bout -------------------
    // 4 passes; per pass each thread owns ONE packed column pair (low regs).
    const float4* wo4 = reinterpret_cast<const float4*>(Wout);   // [DOUT][2]
    const float2* bo2 = reinterpret_cast<const float2*>(bout);
    float2* out2 = reinterpret_cast<float2*>(out);
#pragma unroll
    for (int pass = 0; pass < 4; pass++) {
        const int c0 = pass * 256 + tid * 2;      // first col of the pair
        float4 wa0 = __ldg(&wo4[c0 * 2 + 0]);
        float4 wa1 = __ldg(&wo4[c0 * 2 + 1]);
        float4 wb0 = __ldg(&wo4[(c0 + 1) * 2 + 0]);
        float4 wb1 = __ldg(&wo4[(c0 + 1) * 2 + 1]);
        ull w0 = pk(wa0.x, wb0.x), w1 = pk(wa0.y, wb0.y);
        ull w2 = pk(wa0.z, wb0.z), w3 = pk(wa0.w, wb0.w);
        ull w4 = pk(wa1.x, wb1.x), w5 = pk(wa1.y, wb1.y);
        ull w6 = pk(wa1.z, wb1.z), w7 = pk(wa1.w, wb1.w);
        float2 bv = __ldg(&bo2[c0 >> 1]);
        ull bo = pk(bv.x, bv.y);
#pragma unroll
        for (int r = 0; r < 8; r++) {
            const float* e = &ev_s[r * NQ];
            ull acc = fma2(w0, dup2(e[0]), bo);
            acc = fma2(w1, dup2(e[1]), acc);
            acc = fma2(w2, dup2(e[2]), acc);
            acc = fma2(w3, dup2(e[3]), acc);
            acc = fma2(w4, dup2(e[4]), acc);
            acc = fma2(w5, dup2(e[5]), acc);
            acc = fma2(w6, dup2(e[6]), acc);
            acc = fma2(w7, dup2(e[7]), acc);
            float ox, oy; up2(acc, ox, oy);
            out2[(size_t)(row0 + r) * (DOUT / 2) + (c0 >> 1)] = make_float2(ox, oy);
        }
    }
}

extern "C" void kernel_launch(void* const* d_in, const int* in_sizes, int n_in,
                              void* d_out, int out_size) {
    const float* x    = (const float*)d_in[0];
    const float* Win  = (const float*)d_in[1];
    const float* bin  = (const float*)d_in[2];
    const float* qw   = (const float*)d_in[3];
    const float* Wout = (const float*)d_in[4];
    const float* bout = (const float*)d_in[5];
    float* out = (float*)d_out;

    int B = in_sizes[0] / DIN;            // 8192
    k1_angles<<<B / 8, 128>>>(x, Win, bin, qw);
    k23_circuit_out<<<B / 8, 128>>>(Wout, bout, out);
}